// round 8
// baseline (speedup 1.0000x reference)
#include <cuda_runtime.h>
#include <cuda_fp16.h>
#include <cstdint>

#define FDIM 64
#define TWOF 128
#define NMAX 100000
#define EMAX 2000000
#define BETA 0.5f
#define NEGSLOPE 0.01f

static __device__ __align__(16) __half g_Ph[(size_t)NMAX * TWOF];   // P in fp16
static __device__ __align__(16) __half g_hh[(size_t)NMAX * FDIM];   // h in fp16
static __device__ __align__(16) float g_Wt[FDIM * TWOF];
static __device__ __align__(16) float g_colsum[FDIM];
static __device__ __align__(16) float g_inv[FDIM];
static __device__ unsigned g_mm[4];
// CSR scratch
static __device__ int g_cnt[NMAX];        // histogram, then write-cursors
static __device__ int g_rowptr[NMAX + 1];
static __device__ int g_cur[NMAX];
static __device__ int g_part[128];        // chunk partial sums (<= 98 used)
static __device__ __align__(16) uint2 g_edge[EMAX];  // {dst, ew bits} sorted by src

__device__ __forceinline__ unsigned encf(float f) {
    unsigned u = __float_as_uint(f);
    return (u & 0x80000000u) ? ~u : (u | 0x80000000u);
}
__device__ __forceinline__ float decf(unsigned u) {
    return (u & 0x80000000u) ? __uint_as_float(u & 0x7FFFFFFFu) : __uint_as_float(~u);
}

__device__ __forceinline__ void ffma2(unsigned long long& d, unsigned long long a,
                                      unsigned long long b) {
    asm("fma.rn.f32x2 %0, %1, %2, %3;" : "=l"(d) : "l"(a), "l"(b), "l"(d));
}
__device__ __forceinline__ unsigned long long dup2(float x) {
    unsigned long long d;
    unsigned u = __float_as_uint(x);
    asm("mov.b64 %0, {%1, %1};" : "=l"(d) : "r"(u));
    return d;
}
__device__ __forceinline__ void unpack2(unsigned long long v, float& lo, float& hi) {
    unsigned a, b;
    asm("mov.b64 {%0, %1}, %2;" : "=r"(a), "=r"(b) : "l"(v));
    lo = __uint_as_float(a);
    hi = __uint_as_float(b);
}
__device__ __forceinline__ float4 h4_to_f4(uint2 p) {
    float2 lo = __half22float2(*(__half2*)&p.x);
    float2 hi = __half22float2(*(__half2*)&p.y);
    return make_float4(lo.x, lo.y, hi.x, hi.y);
}
__device__ __forceinline__ float lrelu_ew(float s, float ew) {
    return (s >= 0.f ? s : NEGSLOPE * s) * ew;
}

// ---------- init: zero histogram + colsum + minmax seeds ----------
__global__ void k_init(int N) {
    int i = blockIdx.x * 256 + threadIdx.x;
    if (i < N) g_cnt[i] = 0;
    if (i < FDIM) g_colsum[i] = 0.0f;
    if (i == 0) {
        g_mm[0] = 0xFFFFFFFFu; g_mm[1] = 0u;
        g_mm[2] = 0xFFFFFFFFu; g_mm[3] = 0u;
    }
}

__global__ void k_wprep(const float* __restrict__ fc_w) {
    int idx = blockIdx.x * 256 + threadIdx.x;
    if (idx >= FDIM * TWOF) return;
    int k = idx >> 7, c = idx & 127;
    g_Wt[idx] = (c < FDIM) ? fc_w[c * TWOF + k]
                           : fc_w[(c - FDIM) * TWOF + FDIM + k];
}

__global__ void __launch_bounds__(256) k_hprep(const float* __restrict__ h, int total4) {
    int i = blockIdx.x * 256 + threadIdx.x;
    if (i >= total4) return;
    float4 v = ((const float4*)h)[i];
    __half2 a = __floats2half2_rn(v.x, v.y);
    __half2 b = __floats2half2_rn(v.z, v.w);
    uint2 pk;
    pk.x = *(unsigned*)&a;
    pk.y = *(unsigned*)&b;
    ((uint2*)g_hh)[i] = pk;
}

__global__ void k_minmax(const float* __restrict__ amount,
                         const float* __restrict__ count, int E) {
    int stride = gridDim.x * blockDim.x;
    int i0 = blockIdx.x * blockDim.x + threadIdx.x;
    float amin = INFINITY, amax = -INFINITY, cmin = INFINITY, cmax = -INFINITY;
    int E4 = E >> 2;
    const float4* a4 = (const float4*)amount;
    const float4* c4 = (const float4*)count;
    for (int i = i0; i < E4; i += stride) {
        float4 a = a4[i], c = c4[i];
        amin = fminf(amin, fminf(fminf(a.x, a.y), fminf(a.z, a.w)));
        amax = fmaxf(amax, fmaxf(fmaxf(a.x, a.y), fmaxf(a.z, a.w)));
        cmin = fminf(cmin, fminf(fminf(c.x, c.y), fminf(c.z, c.w)));
        cmax = fmaxf(cmax, fmaxf(fmaxf(c.x, c.y), fmaxf(c.z, c.w)));
    }
    for (int i = (E4 << 2) + i0; i < E; i += stride) {
        float a = amount[i], c = count[i];
        amin = fminf(amin, a); amax = fmaxf(amax, a);
        cmin = fminf(cmin, c); cmax = fmaxf(cmax, c);
    }
    #pragma unroll
    for (int off = 16; off; off >>= 1) {
        amin = fminf(amin, __shfl_down_sync(0xFFFFFFFFu, amin, off));
        amax = fmaxf(amax, __shfl_down_sync(0xFFFFFFFFu, amax, off));
        cmin = fminf(cmin, __shfl_down_sync(0xFFFFFFFFu, cmin, off));
        cmax = fmaxf(cmax, __shfl_down_sync(0xFFFFFFFFu, cmax, off));
    }
    if ((threadIdx.x & 31) == 0) {
        atomicMin(&g_mm[0], encf(amin));
        atomicMax(&g_mm[1], encf(amax));
        atomicMin(&g_mm[2], encf(cmin));
        atomicMax(&g_mm[3], encf(cmax));
    }
}

// ---------- CSR build ----------
__global__ void __launch_bounds__(256) k_hist(const int* __restrict__ adj, int E) {
    int e = blockIdx.x * 256 + threadIdx.x;
    if (e < E) atomicAdd(&g_cnt[adj[e]], 1);
}

// chunk = 1024 counts per block
__global__ void __launch_bounds__(256) k_scanA(int N) {
    int base = blockIdx.x * 1024;
    int t = threadIdx.x;
    int s = 0;
    #pragma unroll
    for (int i = t; i < 1024; i += 256) {
        int idx = base + i;
        s += (idx < N) ? g_cnt[idx] : 0;
    }
    __shared__ int red[256];
    red[t] = s;
    __syncthreads();
    #pragma unroll
    for (int off = 128; off; off >>= 1) {
        if (t < off) red[t] += red[t + off];
        __syncthreads();
    }
    if (t == 0) g_part[blockIdx.x] = red[0];
}

__global__ void k_scanB(int nchunks, int E, int N) {
    if (threadIdx.x == 0) {
        int run = 0;
        for (int i = 0; i < nchunks; i++) {
            int v = g_part[i];
            g_part[i] = run;
            run += v;
        }
        g_rowptr[N] = E;
    }
}

__global__ void __launch_bounds__(256) k_scanC(int N) {
    int b = blockIdx.x, t = threadIdx.x;
    int base = b * 1024 + t * 4;
    int v[4];
    #pragma unroll
    for (int j = 0; j < 4; j++) v[j] = (base + j < N) ? g_cnt[base + j] : 0;
    int local = v[0] + v[1] + v[2] + v[3];
    __shared__ int sums[256];
    sums[t] = local;
    __syncthreads();
    // Hillis-Steele inclusive scan over 256
    #pragma unroll
    for (int off = 1; off < 256; off <<= 1) {
        int x = (t >= off) ? sums[t - off] : 0;
        __syncthreads();
        sums[t] += x;
        __syncthreads();
    }
    int excl = sums[t] - local + g_part[b];
    #pragma unroll
    for (int j = 0; j < 4; j++) {
        if (base + j < N) {
            g_rowptr[base + j] = excl;
            g_cur[base + j] = excl;
        }
        excl += v[j];
    }
}

__global__ void __launch_bounds__(256) k_reorder(const int* __restrict__ adj,
                                                 const float* __restrict__ amount,
                                                 const float* __restrict__ count, int E) {
    int e = blockIdx.x * 256 + threadIdx.x;
    if (e >= E) return;
    float amin = decf(g_mm[0]), amax = decf(g_mm[1]);
    float cmin = decf(g_mm[2]), cmax = decf(g_mm[3]);
    float as = BETA / (amax - amin + 1e-8f);
    float cs = (1.0f - BETA) / (cmax - cmin + 1e-8f);
    int s = adj[e];
    int d = adj[E + e];
    float ew = (amount[e] - amin) * as + (count[e] - cmin) * cs;
    int pos = atomicAdd(&g_cur[s], 1);
    g_edge[pos] = make_uint2((unsigned)d, __float_as_uint(ew));
}

// ---------- projection GEMM (FFMA2, fp16 out) ----------
#define GN 64
__global__ void __launch_bounds__(256) k_gemm(const float* __restrict__ h,
                                              const float* __restrict__ fc_b, int N) {
    __shared__ __align__(16) float hs[GN][68];
    int n0 = blockIdx.x * GN;
    int tid = threadIdx.x;
    {
        const float4* h4 = (const float4*)h;
        for (int idx = tid; idx < GN * (FDIM / 4); idx += 256) {
            int n = idx >> 4, kq = idx & 15;
            int gn = n0 + n;
            float4 v = (gn < N) ? h4[(size_t)gn * (FDIM / 4) + kq]
                                : make_float4(0.f, 0.f, 0.f, 0.f);
            *(float4*)&hs[n][kq * 4] = v;
        }
    }
    __syncthreads();

    int tx = tid & 15, ty = tid >> 4;
    int c0 = tx * 8;
    int nb = ty * 4;

    unsigned long long acc[4][4];
    #pragma unroll
    for (int i = 0; i < 4; i++)
        #pragma unroll
        for (int j = 0; j < 4; j++) acc[i][j] = 0ull;

    #pragma unroll 4
    for (int k = 0; k < FDIM; k++) {
        const ulonglong2* bp = (const ulonglong2*)(g_Wt + k * TWOF + c0);
        ulonglong2 b01 = __ldg(bp);
        ulonglong2 b23 = __ldg(bp + 1);
        #pragma unroll
        for (int i = 0; i < 4; i++) {
            unsigned long long a2 = dup2(hs[nb + i][k]);
            ffma2(acc[i][0], a2, b01.x);
            ffma2(acc[i][1], a2, b01.y);
            ffma2(acc[i][2], a2, b23.x);
            ffma2(acc[i][3], a2, b23.y);
        }
    }

    float bias[8];
    #pragma unroll
    for (int j = 0; j < 8; j++)
        bias[j] = (c0 >= FDIM) ? __ldg(&fc_b[c0 + j - FDIM]) : 0.0f;

    #pragma unroll
    for (int i = 0; i < 4; i++) {
        int gn = n0 + nb + i;
        if (gn >= N) continue;
        float o[8];
        #pragma unroll
        for (int j = 0; j < 4; j++) unpack2(acc[i][j], o[2 * j], o[2 * j + 1]);
        __half2 ha = __floats2half2_rn(o[0] + bias[0], o[1] + bias[1]);
        __half2 hb = __floats2half2_rn(o[2] + bias[2], o[3] + bias[3]);
        __half2 hc = __floats2half2_rn(o[4] + bias[4], o[5] + bias[5]);
        __half2 hd = __floats2half2_rn(o[6] + bias[6], o[7] + bias[7]);
        uint4 pk;
        pk.x = *(unsigned*)&ha; pk.y = *(unsigned*)&hb;
        pk.z = *(unsigned*)&hc; pk.w = *(unsigned*)&hd;
        *(uint4*)(g_Ph + (size_t)gn * TWOF + c0) = pk;
    }
}

// ---------- aggregate: one node per 16-lane group, register accumulate ----------
__global__ void __launch_bounds__(256) k_agg(float* __restrict__ out, int N) {
    int lane16 = threadIdx.x & 15;
    int egrp = threadIdx.x >> 4;
    int co = lane16 * 4;

    float4 cacc = make_float4(0.f, 0.f, 0.f, 0.f);  // colsum partial

    for (int n = blockIdx.x * 16 + egrp; n < N; n += gridDim.x * 16) {
        int e = g_rowptr[n];
        int end = g_rowptr[n + 1];
        float4 p1 = h4_to_f4(*(const uint2*)(g_Ph + (size_t)n * TWOF + co));
        float4 o = make_float4(0.f, 0.f, 0.f, 0.f);

        for (; e + 2 <= end; e += 2) {
            uint2 ed0 = g_edge[e];
            uint2 ed1 = g_edge[e + 1];
            int d0 = (int)ed0.x, d1 = (int)ed1.x;
            float ew0 = __uint_as_float(ed0.y);
            float ew1 = __uint_as_float(ed1.y);
            uint2 q2a = *(const uint2*)(g_Ph + (size_t)d0 * TWOF + FDIM + co);
            uint2 qha = *(const uint2*)(g_hh + (size_t)d0 * FDIM + co);
            uint2 q2b = *(const uint2*)(g_Ph + (size_t)d1 * TWOF + FDIM + co);
            uint2 qhb = *(const uint2*)(g_hh + (size_t)d1 * FDIM + co);

            float4 p2 = h4_to_f4(q2a), hv = h4_to_f4(qha);
            float ex = __expf(lrelu_ew(p1.x + p2.x, ew0));
            float ey = __expf(lrelu_ew(p1.y + p2.y, ew0));
            float ez = __expf(lrelu_ew(p1.z + p2.z, ew0));
            float ew_ = __expf(lrelu_ew(p1.w + p2.w, ew0));
            cacc.x += ex; cacc.y += ey; cacc.z += ez; cacc.w += ew_;
            o.x += ex * hv.x; o.y += ey * hv.y; o.z += ez * hv.z; o.w += ew_ * hv.w;

            float4 p2b = h4_to_f4(q2b), hvb = h4_to_f4(qhb);
            float fx = __expf(lrelu_ew(p1.x + p2b.x, ew1));
            float fy = __expf(lrelu_ew(p1.y + p2b.y, ew1));
            float fz = __expf(lrelu_ew(p1.z + p2b.z, ew1));
            float fw = __expf(lrelu_ew(p1.w + p2b.w, ew1));
            cacc.x += fx; cacc.y += fy; cacc.z += fz; cacc.w += fw;
            o.x += fx * hvb.x; o.y += fy * hvb.y; o.z += fz * hvb.z; o.w += fw * hvb.w;
        }
        if (e < end) {
            uint2 ed0 = g_edge[e];
            int d0 = (int)ed0.x;
            float ew0 = __uint_as_float(ed0.y);
            float4 p2 = h4_to_f4(*(const uint2*)(g_Ph + (size_t)d0 * TWOF + FDIM + co));
            float4 hv = h4_to_f4(*(const uint2*)(g_hh + (size_t)d0 * FDIM + co));
            float ex = __expf(lrelu_ew(p1.x + p2.x, ew0));
            float ey = __expf(lrelu_ew(p1.y + p2.y, ew0));
            float ez = __expf(lrelu_ew(p1.z + p2.z, ew0));
            float ew_ = __expf(lrelu_ew(p1.w + p2.w, ew0));
            cacc.x += ex; cacc.y += ey; cacc.z += ez; cacc.w += ew_;
            o.x += ex * hv.x; o.y += ey * hv.y; o.z += ez * hv.z; o.w += ew_ * hv.w;
        }
        *(float4*)(out + (size_t)n * FDIM + co) = o;  // unnormalized
    }

    __shared__ float scol[FDIM];
    if (threadIdx.x < FDIM) scol[threadIdx.x] = 0.0f;
    __syncthreads();
    atomicAdd(&scol[co + 0], cacc.x);
    atomicAdd(&scol[co + 1], cacc.y);
    atomicAdd(&scol[co + 2], cacc.z);
    atomicAdd(&scol[co + 3], cacc.w);
    __syncthreads();
    if (threadIdx.x < FDIM) atomicAdd(&g_colsum[threadIdx.x], scol[threadIdx.x]);
}

__global__ void k_inv() {
    int t = threadIdx.x;
    if (t < FDIM) g_inv[t] = 1.0f / g_colsum[t];
}

__global__ void __launch_bounds__(256) k_norm(float* __restrict__ out, int total4) {
    int i = blockIdx.x * blockDim.x + threadIdx.x;
    if (i >= total4) return;
    float4 inv = *(const float4*)(g_inv + (i & 15) * 4);
    float4 v = ((float4*)out)[i];
    v.x *= inv.x; v.y *= inv.y; v.z *= inv.z; v.w *= inv.w;
    ((float4*)out)[i] = v;
}

extern "C" void kernel_launch(void* const* d_in, const int* in_sizes, int n_in,
                              void* d_out, int out_size) {
    const float* h = (const float*)d_in[0];
    const int* adj = (const int*)d_in[1];
    const float* amount = (const float*)d_in[2];
    const float* count = (const float*)d_in[3];
    const float* fc_w = (const float*)d_in[4];
    const float* fc_b = (const float*)d_in[5];
    float* out = (float*)d_out;

    int N = in_sizes[0] / FDIM;
    int E = in_sizes[2];
    int htotal4 = (N * FDIM) / 4;
    int nchunks = (N + 1023) / 1024;

    k_init<<<(N + 255) / 256, 256>>>(N);
    k_wprep<<<(FDIM * TWOF + 255) / 256, 256>>>(fc_w);
    k_hprep<<<(htotal4 + 255) / 256, 256>>>(h, htotal4);
    k_minmax<<<2048, 256>>>(amount, count, E);
    k_hist<<<(E + 255) / 256, 256>>>(adj, E);
    k_scanA<<<nchunks, 256>>>(N);
    k_scanB<<<1, 32>>>(nchunks, E, N);
    k_scanC<<<nchunks, 256>>>(N);
    k_gemm<<<(N + GN - 1) / GN, 256>>>(h, fc_b, N);
    k_reorder<<<(E + 255) / 256, 256>>>(adj, amount, count, E);
    k_agg<<<(N + 15) / 16, 256>>>(out, N);
    k_inv<<<1, 64>>>();
    int total4 = out_size / 4;
    k_norm<<<(total4 + 255) / 256, 256>>>(out, total4);
}

// round 9
// speedup vs baseline: 1.3016x; 1.3016x over previous
#include <cuda_runtime.h>
#include <cuda_fp16.h>
#include <cstdint>

#define FDIM 64
#define TWOF 128
#define NMAX 100000
#define EMAX 2000000
#define BETA 0.5f
#define NEGSLOPE 0.01f

static __device__ __align__(16) __half g_Ph[(size_t)NMAX * TWOF];   // P in fp16
static __device__ __align__(16) __half g_hh[(size_t)NMAX * FDIM];   // h in fp16
static __device__ __align__(16) float g_Wt[FDIM * TWOF];
static __device__ __align__(16) float g_colsum[FDIM];
static __device__ unsigned g_mm[4];
// CSR scratch
static __device__ int g_cnt[NMAX];
static __device__ int g_rowptr[NMAX + 1];
static __device__ int g_cur[NMAX];
static __device__ int g_part[128];
static __device__ __align__(16) uint2 g_edge[EMAX];  // {dst, ew bits} grouped by src

// k_prep block partition
#define MM_BLKS 128
#define HIST_BLKS 256
#define HPREP_BLKS 256
#define WPREP_BLKS 32
#define PREP_BLKS (MM_BLKS + HIST_BLKS + HPREP_BLKS + WPREP_BLKS)
#define RE_BLKS 512

__device__ __forceinline__ unsigned encf(float f) {
    unsigned u = __float_as_uint(f);
    return (u & 0x80000000u) ? ~u : (u | 0x80000000u);
}
__device__ __forceinline__ float decf(unsigned u) {
    return (u & 0x80000000u) ? __uint_as_float(u & 0x7FFFFFFFu) : __uint_as_float(~u);
}
__device__ __forceinline__ void ffma2(unsigned long long& d, unsigned long long a,
                                      unsigned long long b) {
    asm("fma.rn.f32x2 %0, %1, %2, %3;" : "=l"(d) : "l"(a), "l"(b), "l"(d));
}
__device__ __forceinline__ unsigned long long dup2(float x) {
    unsigned long long d;
    unsigned u = __float_as_uint(x);
    asm("mov.b64 %0, {%1, %1};" : "=l"(d) : "r"(u));
    return d;
}
__device__ __forceinline__ void unpack2(unsigned long long v, float& lo, float& hi) {
    unsigned a, b;
    asm("mov.b64 {%0, %1}, %2;" : "=r"(a), "=r"(b) : "l"(v));
    lo = __uint_as_float(a);
    hi = __uint_as_float(b);
}
__device__ __forceinline__ float4 h4_to_f4(uint2 p) {
    float2 lo = __half22float2(*(__half2*)&p.x);
    float2 hi = __half22float2(*(__half2*)&p.y);
    return make_float4(lo.x, lo.y, hi.x, hi.y);
}
__device__ __forceinline__ float lrelu_ew(float s, float ew) {
    return (s >= 0.f ? s : NEGSLOPE * s) * ew;
}

// ---------- init ----------
__global__ void k_init(int N) {
    int i = blockIdx.x * 256 + threadIdx.x;
    if (i < N) g_cnt[i] = 0;
    if (i < FDIM) g_colsum[i] = 0.0f;
    if (i == 0) {
        g_mm[0] = 0xFFFFFFFFu; g_mm[1] = 0u;
        g_mm[2] = 0xFFFFFFFFu; g_mm[3] = 0u;
    }
}

// ---------- fused prep: minmax | hist | h->fp16 | weight transpose ----------
__global__ void __launch_bounds__(256) k_prep(const float* __restrict__ amount,
                                              const float* __restrict__ count,
                                              const int* __restrict__ adj,
                                              const float* __restrict__ h,
                                              const float* __restrict__ fc_w,
                                              int E, int N) {
    int b = blockIdx.x;
    int tid = threadIdx.x;

    if (b < MM_BLKS) {
        // --- minmax, block-level reduction, 4 global atomics per block ---
        int stride = MM_BLKS * 256;
        float amin = INFINITY, amax = -INFINITY, cmin = INFINITY, cmax = -INFINITY;
        int E4 = E >> 2;
        const float4* a4 = (const float4*)amount;
        const float4* c4 = (const float4*)count;
        for (int i = b * 256 + tid; i < E4; i += stride) {
            float4 a = a4[i], c = c4[i];
            amin = fminf(amin, fminf(fminf(a.x, a.y), fminf(a.z, a.w)));
            amax = fmaxf(amax, fmaxf(fmaxf(a.x, a.y), fmaxf(a.z, a.w)));
            cmin = fminf(cmin, fminf(fminf(c.x, c.y), fminf(c.z, c.w)));
            cmax = fmaxf(cmax, fmaxf(fmaxf(c.x, c.y), fmaxf(c.z, c.w)));
        }
        if (b == 0) {
            for (int i = (E4 << 2) + tid; i < E; i += 256) {
                float a = amount[i], c = count[i];
                amin = fminf(amin, a); amax = fmaxf(amax, a);
                cmin = fminf(cmin, c); cmax = fmaxf(cmax, c);
            }
        }
        #pragma unroll
        for (int off = 16; off; off >>= 1) {
            amin = fminf(amin, __shfl_down_sync(0xFFFFFFFFu, amin, off));
            amax = fmaxf(amax, __shfl_down_sync(0xFFFFFFFFu, amax, off));
            cmin = fminf(cmin, __shfl_down_sync(0xFFFFFFFFu, cmin, off));
            cmax = fmaxf(cmax, __shfl_down_sync(0xFFFFFFFFu, cmax, off));
        }
        __shared__ float red[4][8];
        int w = tid >> 5, l = tid & 31;
        if (l == 0) {
            red[0][w] = amin; red[1][w] = amax;
            red[2][w] = cmin; red[3][w] = cmax;
        }
        __syncthreads();
        if (tid == 0) {
            #pragma unroll
            for (int i = 1; i < 8; i++) {
                red[0][0] = fminf(red[0][0], red[0][i]);
                red[1][0] = fmaxf(red[1][0], red[1][i]);
                red[2][0] = fminf(red[2][0], red[2][i]);
                red[3][0] = fmaxf(red[3][0], red[3][i]);
            }
            atomicMin(&g_mm[0], encf(red[0][0]));
            atomicMax(&g_mm[1], encf(red[1][0]));
            atomicMin(&g_mm[2], encf(red[2][0]));
            atomicMax(&g_mm[3], encf(red[3][0]));
        }
    } else if (b < MM_BLKS + HIST_BLKS) {
        // --- histogram of src ---
        int rb = b - MM_BLKS;
        int stride = HIST_BLKS * 256;
        int E4 = E >> 2;
        const int4* a4 = (const int4*)adj;
        for (int i = rb * 256 + tid; i < E4; i += stride) {
            int4 s = a4[i];
            atomicAdd(&g_cnt[s.x], 1);
            atomicAdd(&g_cnt[s.y], 1);
            atomicAdd(&g_cnt[s.z], 1);
            atomicAdd(&g_cnt[s.w], 1);
        }
        if (rb == 0 && tid < (E & 3)) atomicAdd(&g_cnt[adj[(E & ~3) + tid]], 1);
    } else if (b < MM_BLKS + HIST_BLKS + HPREP_BLKS) {
        // --- h -> fp16 ---
        int rb = b - MM_BLKS - HIST_BLKS;
        int stride = HPREP_BLKS * 256;
        int total4 = (N * FDIM) >> 2;
        for (int i = rb * 256 + tid; i < total4; i += stride) {
            float4 v = ((const float4*)h)[i];
            __half2 a = __floats2half2_rn(v.x, v.y);
            __half2 bb = __floats2half2_rn(v.z, v.w);
            uint2 pk;
            pk.x = *(unsigned*)&a;
            pk.y = *(unsigned*)&bb;
            ((uint2*)g_hh)[i] = pk;
        }
    } else {
        // --- weight transpose ---
        int idx = (b - MM_BLKS - HIST_BLKS - HPREP_BLKS) * 256 + tid;
        if (idx < FDIM * TWOF) {
            int k = idx >> 7, c = idx & 127;
            g_Wt[idx] = (c < FDIM) ? fc_w[c * TWOF + k]
                                   : fc_w[(c - FDIM) * TWOF + FDIM + k];
        }
    }
}

// ---------- scans ----------
__global__ void __launch_bounds__(256) k_scanA(int N) {
    int base = blockIdx.x * 1024;
    int t = threadIdx.x;
    int s = 0;
    #pragma unroll
    for (int i = t; i < 1024; i += 256) {
        int idx = base + i;
        s += (idx < N) ? g_cnt[idx] : 0;
    }
    __shared__ int red[256];
    red[t] = s;
    __syncthreads();
    #pragma unroll
    for (int off = 128; off; off >>= 1) {
        if (t < off) red[t] += red[t + off];
        __syncthreads();
    }
    if (t == 0) g_part[blockIdx.x] = red[0];
}

__global__ void k_scanB(int nchunks, int E, int N) {
    if (threadIdx.x == 0) {
        int run = 0;
        for (int i = 0; i < nchunks; i++) {
            int v = g_part[i];
            g_part[i] = run;
            run += v;
        }
        g_rowptr[N] = E;
    }
}

__global__ void __launch_bounds__(256) k_scanC(int N) {
    int b = blockIdx.x, t = threadIdx.x;
    int base = b * 1024 + t * 4;
    int v[4];
    #pragma unroll
    for (int j = 0; j < 4; j++) v[j] = (base + j < N) ? g_cnt[base + j] : 0;
    int local = v[0] + v[1] + v[2] + v[3];
    __shared__ int sums[256];
    sums[t] = local;
    __syncthreads();
    #pragma unroll
    for (int off = 1; off < 256; off <<= 1) {
        int x = (t >= off) ? sums[t - off] : 0;
        __syncthreads();
        sums[t] += x;
        __syncthreads();
    }
    int excl = sums[t] - local + g_part[b];
    #pragma unroll
    for (int j = 0; j < 4; j++) {
        if (base + j < N) {
            g_rowptr[base + j] = excl;
            g_cur[base + j] = excl;
        }
        excl += v[j];
    }
}

// ---------- fused main: GEMM | edge reorder ----------
#define GN 64
__global__ void __launch_bounds__(256) k_main(const float* __restrict__ h,
                                              const float* __restrict__ fc_b,
                                              const int* __restrict__ adj,
                                              const float* __restrict__ amount,
                                              const float* __restrict__ count,
                                              int E, int N, int gemmBlocks) {
    __shared__ __align__(16) float hs[GN][68];
    int tid = threadIdx.x;

    if ((int)blockIdx.x < gemmBlocks) {
        int n0 = blockIdx.x * GN;
        {
            const float4* h4 = (const float4*)h;
            for (int idx = tid; idx < GN * (FDIM / 4); idx += 256) {
                int n = idx >> 4, kq = idx & 15;
                int gn = n0 + n;
                float4 v = (gn < N) ? h4[(size_t)gn * (FDIM / 4) + kq]
                                    : make_float4(0.f, 0.f, 0.f, 0.f);
                *(float4*)&hs[n][kq * 4] = v;
            }
        }
        __syncthreads();

        int tx = tid & 15, ty = tid >> 4;
        int c0 = tx * 8;
        int nb = ty * 4;

        unsigned long long acc[4][4];
        #pragma unroll
        for (int i = 0; i < 4; i++)
            #pragma unroll
            for (int j = 0; j < 4; j++) acc[i][j] = 0ull;

        #pragma unroll 4
        for (int k = 0; k < FDIM; k++) {
            const ulonglong2* bp = (const ulonglong2*)(g_Wt + k * TWOF + c0);
            ulonglong2 b01 = __ldg(bp);
            ulonglong2 b23 = __ldg(bp + 1);
            #pragma unroll
            for (int i = 0; i < 4; i++) {
                unsigned long long a2 = dup2(hs[nb + i][k]);
                ffma2(acc[i][0], a2, b01.x);
                ffma2(acc[i][1], a2, b01.y);
                ffma2(acc[i][2], a2, b23.x);
                ffma2(acc[i][3], a2, b23.y);
            }
        }

        float bias[8];
        #pragma unroll
        for (int j = 0; j < 8; j++)
            bias[j] = (c0 >= FDIM) ? __ldg(&fc_b[c0 + j - FDIM]) : 0.0f;

        #pragma unroll
        for (int i = 0; i < 4; i++) {
            int gn = n0 + nb + i;
            if (gn >= N) continue;
            float o[8];
            #pragma unroll
            for (int j = 0; j < 4; j++) unpack2(acc[i][j], o[2 * j], o[2 * j + 1]);
            __half2 ha = __floats2half2_rn(o[0] + bias[0], o[1] + bias[1]);
            __half2 hb = __floats2half2_rn(o[2] + bias[2], o[3] + bias[3]);
            __half2 hc = __floats2half2_rn(o[4] + bias[4], o[5] + bias[5]);
            __half2 hd = __floats2half2_rn(o[6] + bias[6], o[7] + bias[7]);
            uint4 pk;
            pk.x = *(unsigned*)&ha; pk.y = *(unsigned*)&hb;
            pk.z = *(unsigned*)&hc; pk.w = *(unsigned*)&hd;
            *(uint4*)(g_Ph + (size_t)gn * TWOF + c0) = pk;
        }
    } else {
        // --- edge reorder into CSR order, ew precomputed ---
        int rb = blockIdx.x - gemmBlocks;
        float amin = decf(g_mm[0]), amax = decf(g_mm[1]);
        float cmin = decf(g_mm[2]), cmax = decf(g_mm[3]);
        float as = BETA / (amax - amin + 1e-8f);
        float cs = (1.0f - BETA) / (cmax - cmin + 1e-8f);
        int stride = RE_BLKS * 256;
        for (int e = rb * 256 + tid; e < E; e += stride) {
            int s = adj[e];
            int d = adj[E + e];
            float ew = (amount[e] - amin) * as + (count[e] - cmin) * cs;
            int pos = atomicAdd(&g_cur[s], 1);
            g_edge[pos] = make_uint2((unsigned)d, __float_as_uint(ew));
        }
    }
}

// ---------- aggregate: one node per 16-lane group, 4-edge unroll ----------
__global__ void __launch_bounds__(256) k_agg(float* __restrict__ out, int N) {
    int lane16 = threadIdx.x & 15;
    int egrp = threadIdx.x >> 4;
    int co = lane16 * 4;

    float4 cacc = make_float4(0.f, 0.f, 0.f, 0.f);

    for (int n = blockIdx.x * 16 + egrp; n < N; n += gridDim.x * 16) {
        int e = g_rowptr[n];
        int end = g_rowptr[n + 1];
        float4 p1 = h4_to_f4(*(const uint2*)(g_Ph + (size_t)n * TWOF + co));
        float4 o = make_float4(0.f, 0.f, 0.f, 0.f);

        for (; e + 4 <= end; e += 4) {
            uint2 ed0 = __ldg(&g_edge[e]);
            uint2 ed1 = __ldg(&g_edge[e + 1]);
            uint2 ed2 = __ldg(&g_edge[e + 2]);
            uint2 ed3 = __ldg(&g_edge[e + 3]);
            uint2 q2a = *(const uint2*)(g_Ph + (size_t)(int)ed0.x * TWOF + FDIM + co);
            uint2 qha = *(const uint2*)(g_hh + (size_t)(int)ed0.x * FDIM + co);
            uint2 q2b = *(const uint2*)(g_Ph + (size_t)(int)ed1.x * TWOF + FDIM + co);
            uint2 qhb = *(const uint2*)(g_hh + (size_t)(int)ed1.x * FDIM + co);
            uint2 q2c = *(const uint2*)(g_Ph + (size_t)(int)ed2.x * TWOF + FDIM + co);
            uint2 qhc = *(const uint2*)(g_hh + (size_t)(int)ed2.x * FDIM + co);
            uint2 q2d = *(const uint2*)(g_Ph + (size_t)(int)ed3.x * TWOF + FDIM + co);
            uint2 qhd = *(const uint2*)(g_hh + (size_t)(int)ed3.x * FDIM + co);

            float ew0 = __uint_as_float(ed0.y);
            float ew1 = __uint_as_float(ed1.y);
            float ew2 = __uint_as_float(ed2.y);
            float ew3 = __uint_as_float(ed3.y);

            {
                float4 p2 = h4_to_f4(q2a), hv = h4_to_f4(qha);
                float ex = __expf(lrelu_ew(p1.x + p2.x, ew0));
                float ey = __expf(lrelu_ew(p1.y + p2.y, ew0));
                float ez = __expf(lrelu_ew(p1.z + p2.z, ew0));
                float ew_ = __expf(lrelu_ew(p1.w + p2.w, ew0));
                cacc.x += ex; cacc.y += ey; cacc.z += ez; cacc.w += ew_;
                o.x += ex * hv.x; o.y += ey * hv.y; o.z += ez * hv.z; o.w += ew_ * hv.w;
            }
            {
                float4 p2 = h4_to_f4(q2b), hv = h4_to_f4(qhb);
                float ex = __expf(lrelu_ew(p1.x + p2.x, ew1));
                float ey = __expf(lrelu_ew(p1.y + p2.y, ew1));
                float ez = __expf(lrelu_ew(p1.z + p2.z, ew1));
                float ew_ = __expf(lrelu_ew(p1.w + p2.w, ew1));
                cacc.x += ex; cacc.y += ey; cacc.z += ez; cacc.w += ew_;
                o.x += ex * hv.x; o.y += ey * hv.y; o.z += ez * hv.z; o.w += ew_ * hv.w;
            }
            {
                float4 p2 = h4_to_f4(q2c), hv = h4_to_f4(qhc);
                float ex = __expf(lrelu_ew(p1.x + p2.x, ew2));
                float ey = __expf(lrelu_ew(p1.y + p2.y, ew2));
                float ez = __expf(lrelu_ew(p1.z + p2.z, ew2));
                float ew_ = __expf(lrelu_ew(p1.w + p2.w, ew2));
                cacc.x += ex; cacc.y += ey; cacc.z += ez; cacc.w += ew_;
                o.x += ex * hv.x; o.y += ey * hv.y; o.z += ez * hv.z; o.w += ew_ * hv.w;
            }
            {
                float4 p2 = h4_to_f4(q2d), hv = h4_to_f4(qhd);
                float ex = __expf(lrelu_ew(p1.x + p2.x, ew3));
                float ey = __expf(lrelu_ew(p1.y + p2.y, ew3));
                float ez = __expf(lrelu_ew(p1.z + p2.z, ew3));
                float ew_ = __expf(lrelu_ew(p1.w + p2.w, ew3));
                cacc.x += ex; cacc.y += ey; cacc.z += ez; cacc.w += ew_;
                o.x += ex * hv.x; o.y += ey * hv.y; o.z += ez * hv.z; o.w += ew_ * hv.w;
            }
        }
        for (; e < end; e++) {
            uint2 ed0 = __ldg(&g_edge[e]);
            int d0 = (int)ed0.x;
            float ew0 = __uint_as_float(ed0.y);
            float4 p2 = h4_to_f4(*(const uint2*)(g_Ph + (size_t)d0 * TWOF + FDIM + co));
            float4 hv = h4_to_f4(*(const uint2*)(g_hh + (size_t)d0 * FDIM + co));
            float ex = __expf(lrelu_ew(p1.x + p2.x, ew0));
            float ey = __expf(lrelu_ew(p1.y + p2.y, ew0));
            float ez = __expf(lrelu_ew(p1.z + p2.z, ew0));
            float ew_ = __expf(lrelu_ew(p1.w + p2.w, ew0));
            cacc.x += ex; cacc.y += ey; cacc.z += ez; cacc.w += ew_;
            o.x += ex * hv.x; o.y += ey * hv.y; o.z += ez * hv.z; o.w += ew_ * hv.w;
        }
        *(float4*)(out + (size_t)n * FDIM + co) = o;
    }

    __shared__ float scol[FDIM];
    if (threadIdx.x < FDIM) scol[threadIdx.x] = 0.0f;
    __syncthreads();
    atomicAdd(&scol[co + 0], cacc.x);
    atomicAdd(&scol[co + 1], cacc.y);
    atomicAdd(&scol[co + 2], cacc.z);
    atomicAdd(&scol[co + 3], cacc.w);
    __syncthreads();
    if (threadIdx.x < FDIM) atomicAdd(&g_colsum[threadIdx.x], scol[threadIdx.x]);
}

// ---------- normalize: out[n][c] /= colsum[c] (reciprocal inline) ----------
__global__ void __launch_bounds__(256) k_norm(float* __restrict__ out, int total4) {
    int i = blockIdx.x * blockDim.x + threadIdx.x;
    if (i >= total4) return;
    float4 cs4 = *(const float4*)(g_colsum + (i & 15) * 4);
    float4 v = ((float4*)out)[i];
    v.x = v.x / cs4.x;
    v.y = v.y / cs4.y;
    v.z = v.z / cs4.z;
    v.w = v.w / cs4.w;
    ((float4*)out)[i] = v;
}

extern "C" void kernel_launch(void* const* d_in, const int* in_sizes, int n_in,
                              void* d_out, int out_size) {
    const float* h = (const float*)d_in[0];
    const int* adj = (const int*)d_in[1];
    const float* amount = (const float*)d_in[2];
    const float* count = (const float*)d_in[3];
    const float* fc_w = (const float*)d_in[4];
    const float* fc_b = (const float*)d_in[5];
    float* out = (float*)d_out;

    int N = in_sizes[0] / FDIM;
    int E = in_sizes[2];
    int nchunks = (N + 1023) / 1024;
    int gemmBlocks = (N + GN - 1) / GN;

    k_init<<<(N + 255) / 256, 256>>>(N);
    k_prep<<<PREP_BLKS, 256>>>(amount, count, adj, h, fc_w, E, N);
    k_scanA<<<nchunks, 256>>>(N);
    k_scanB<<<1, 32>>>(nchunks, E, N);
    k_scanC<<<nchunks, 256>>>(N);
    k_main<<<gemmBlocks + RE_BLKS, 256>>>(h, fc_b, adj, amount, count, E, N, gemmBlocks);
    k_agg<<<(N + 15) / 16, 256>>>(out, N);
    int total4 = out_size / 4;
    k_norm<<<(total4 + 255) / 256, 256>>>(out, total4);
}